// round 14
// baseline (speedup 1.0000x reference)
#include <cuda_runtime.h>
#include <cuda_bf16.h>
#include <cstdint>

#define NEG_INF_F (-1.0e12f)

constexpr int S_  = 1024;
constexpr int D_  = 128;
constexpr int BH_ = 32;   // B*H

// Approx scores (bf16), candidate indices/counts, approx (rowmax, tau).
static __device__ __align__(16) __nv_bfloat16 g_scores[(size_t)BH_ * S_ * S_];
static __device__ uint16_t g_pidx [(size_t)BH_ * S_ * S_];
static __device__ int      g_count[(size_t)BH_ * S_];
static __device__ float2   g_mt   [(size_t)BH_ * S_];

// ---------------------------------------------------------------------------
// PTX helpers
// ---------------------------------------------------------------------------
__device__ __forceinline__ void ldsm4(uint32_t* r, uint32_t addr) {
    asm volatile("ldmatrix.sync.aligned.m8n8.x4.shared.b16 {%0,%1,%2,%3}, [%4];\n"
                 : "=r"(r[0]), "=r"(r[1]), "=r"(r[2]), "=r"(r[3]) : "r"(addr));
}
__device__ __forceinline__ void mma_bf16(float* c, const uint32_t* a,
                                         uint32_t b0, uint32_t b1) {
    asm volatile("mma.sync.aligned.m16n8k16.row.col.f32.bf16.bf16.f32 "
                 "{%0,%1,%2,%3}, {%4,%5,%6,%7}, {%8,%9}, {%0,%1,%2,%3};\n"
                 : "+f"(c[0]), "+f"(c[1]), "+f"(c[2]), "+f"(c[3])
                 : "r"(a[0]), "r"(a[1]), "r"(a[2]), "r"(a[3]), "r"(b0), "r"(b1));
}
__device__ __forceinline__ uint32_t cvt2(float a, float b) {
    __nv_bfloat162 h = __floats2bfloat162_rn(a, b);
    return *(uint32_t*)&h;
}

// ---------------------------------------------------------------------------
// Kernel 1: approx scores (bf16) = mask ? scale * Q K^T : -1e12
// (round-12 version, measured 80.4us: 64x128 tile, single-plane bf16 MMA,
//  BK=32 double-buffered smem, distance-2 register pipeline, 2 CTAs/SM)
// ---------------------------------------------------------------------------
__global__ void __launch_bounds__(256, 2) qk_kernel(const float* __restrict__ q,
                                                    const float* __restrict__ k,
                                                    const int*   __restrict__ mask) {
    extern __shared__ __align__(16) uint8_t sm[];
    constexpr uint32_t QH = 0, KH = 5120, BUF = 15360;
    const uint32_t sb = (uint32_t)__cvta_generic_to_shared(sm);

    const int tid  = threadIdx.x;
    const int lane = tid & 31;
    const int wid  = tid >> 5;
    const int wm   = wid & 1;
    const int wn   = wid >> 1;
    const int bh   = blockIdx.z;
    const int b    = bh >> 3;
    const int row0 = blockIdx.x << 6;
    const int col0 = blockIdx.y << 7;

    const int pr = tid >> 3;
    const int pc = (tid & 7) << 2;
    const float* qp0 = q + ((size_t)bh * S_ + row0 + pr) * D_ + pc;
    const float* qp1 = qp0 + (size_t)32 * D_;
    const float* kp  = k + ((size_t)bh * S_ + col0 + pr) * D_ + pc;

    float4 Qr[2][2], Kr[2][4];

    auto load_chunk = [&](int c, int s) {
        Qr[s][0] = *(const float4*)(qp0 + c * 32);
        Qr[s][1] = *(const float4*)(qp1 + c * 32);
        #pragma unroll
        for (int i = 0; i < 4; ++i)
            Kr[s][i] = *(const float4*)(kp + (size_t)(32 * i) * D_ + c * 32);
    };
    auto store_chunk = [&](int s, int buf) {
        uint8_t* B = sm + (uint32_t)buf * BUF;
        #pragma unroll
        for (int i = 0; i < 2; ++i) {
            float4 vq = Qr[s][i];
            uint32_t off = 2u * ((uint32_t)(pr + 32 * i) * 40 + pc);
            *(uint2*)(B + QH + off) = make_uint2(cvt2(vq.x, vq.y), cvt2(vq.z, vq.w));
        }
        #pragma unroll
        for (int i = 0; i < 4; ++i) {
            float4 vk = Kr[s][i];
            uint32_t off = 2u * ((uint32_t)(pr + 32 * i) * 40 + pc);
            *(uint2*)(B + KH + off) = make_uint2(cvt2(vk.x, vk.y), cvt2(vk.z, vk.w));
        }
    };

    const int lrA = lane & 15, lcA = (lane >> 4) << 3;
    const int lrB = ((lane >> 4) << 3) + (lane & 7), lcB = ((lane >> 3) & 1) << 3;
    uint32_t aAddr[2], bAddr[2];
    #pragma unroll
    for (int mi = 0; mi < 2; ++mi)
        aAddr[mi] = sb + QH + 2u * ((uint32_t)(wm * 32 + mi * 16 + lrA) * 40 + lcA);
    #pragma unroll
    for (int nt = 0; nt < 2; ++nt)
        bAddr[nt] = sb + KH + 2u * ((uint32_t)(wn * 32 + nt * 16 + lrB) * 40 + lcB);

    load_chunk(0, 0);
    store_chunk(0, 0);
    load_chunk(1, 1);
    __syncthreads();

    float acc[2][4][4] = {};
    constexpr int NC = D_ / 32;

    #pragma unroll
    for (int c = 0; c < NC; ++c) {
        const int buf = c & 1;
        if (c + 2 < NC) load_chunk(c + 2, buf);

        const uint32_t bo = (uint32_t)buf * BUF;
        #pragma unroll
        for (int kk = 0; kk < 2; ++kk) {
            const uint32_t ko = 32u * kk;
            uint32_t Ah[2][4], Bh[2][4];
            ldsm4(Ah[0], aAddr[0] + bo + ko);
            ldsm4(Ah[1], aAddr[1] + bo + ko);
            ldsm4(Bh[0], bAddr[0] + bo + ko);
            ldsm4(Bh[1], bAddr[1] + bo + ko);
            #pragma unroll
            for (int mi = 0; mi < 2; ++mi)
                #pragma unroll
                for (int ni = 0; ni < 4; ++ni)
                    mma_bf16(acc[mi][ni], Ah[mi],
                             Bh[ni >> 1][(ni & 1) * 2], Bh[ni >> 1][(ni & 1) * 2 + 1]);
        }

        if (c + 1 < NC) store_chunk((c + 1) & 1, (c + 1) & 1);
        __syncthreads();
    }

    const float scale = 0.08838834764831845f;
    __nv_bfloat16* srow = g_scores + (size_t)bh * S_ * S_;
    const int*     mrow = mask     + (size_t)b  * S_ * S_;
    const int      rb   = row0 + wm * 32 + (lane >> 2);
    const int      cb   = col0 + wn * 32 + ((lane & 3) << 1);

    #pragma unroll
    for (int mi = 0; mi < 2; ++mi)
        #pragma unroll
        for (int h = 0; h < 2; ++h) {
            int r = rb + mi * 16 + h * 8;
            #pragma unroll
            for (int ni = 0; ni < 4; ++ni) {
                int cc = cb + ni * 8;
                int2 mk = *(const int2*)(mrow + (size_t)r * S_ + cc);
                float f0 = mk.x ? acc[mi][ni][2 * h]     * scale : NEG_INF_F;
                float f1 = mk.y ? acc[mi][ni][2 * h + 1] * scale : NEG_INF_F;
                *(__nv_bfloat162*)(srow + (size_t)r * S_ + cc) =
                    __floats2bfloat162_rn(f0, f1);
            }
        }
}

// ---------------------------------------------------------------------------
// Kernel 2: approx entmax tau + candidate selection (margin 0.1), warp/row.
// Stores (approx rowmax, approx tau) for the exact Newton warm start.
// ---------------------------------------------------------------------------
__global__ void __launch_bounds__(512) entmax_kernel() {
    const int tid  = threadIdx.x;
    const int lane = tid & 31;
    const int wid  = tid >> 5;
    const size_t row = (size_t)blockIdx.x * 16 + wid;

    const uint4* rowp = (const uint4*)(g_scores + row * S_);

    float x[32];
    float m = -3.4e38f;
    #pragma unroll
    for (int j = 0; j < 4; ++j) {
        uint4 w = rowp[(j << 5) + lane];
        float2 f0 = __bfloat1622float2(*(__nv_bfloat162*)&w.x);
        float2 f1 = __bfloat1622float2(*(__nv_bfloat162*)&w.y);
        float2 f2 = __bfloat1622float2(*(__nv_bfloat162*)&w.z);
        float2 f3 = __bfloat1622float2(*(__nv_bfloat162*)&w.w);
        x[j*8+0] = f0.x; x[j*8+1] = f0.y; x[j*8+2] = f1.x; x[j*8+3] = f1.y;
        x[j*8+4] = f2.x; x[j*8+5] = f2.y; x[j*8+6] = f3.x; x[j*8+7] = f3.y;
        #pragma unroll
        for (int e = 0; e < 8; ++e) m = fmaxf(m, x[j*8+e]);
    }
    #pragma unroll
    for (int o = 16; o; o >>= 1) m = fmaxf(m, __shfl_xor_sync(0xffffffffu, m, o));

    #pragma unroll
    for (int e = 0; e < 32; ++e) x[e] = (x[e] - m) * 0.5f;

    float tau = -1.0f;
    for (int it = 0; it < 16; ++it) {
        float s1 = 0.0f, s2 = 0.0f;
        #pragma unroll
        for (int e = 0; e < 32; ++e) {
            float t = fmaxf(x[e] - tau, 0.0f);
            s1 += t;
            s2 = fmaf(t, t, s2);
        }
        #pragma unroll
        for (int o = 16; o; o >>= 1) {
            s1 += __shfl_xor_sync(0xffffffffu, s1, o);
            s2 += __shfl_xor_sync(0xffffffffu, s2, o);
        }
        tau += (s2 - 1.0f) / (2.0f * s1);
        tau  = fminf(tau, -0.03125f);
        if (fabsf(s2 - 1.0f) < 1e-4f) break;
    }

    const float thr = tau - 0.1f;
    uint16_t* pi = g_pidx + (row << 10);
    int base = 0;
    #pragma unroll
    for (int j = 0; j < 4; ++j)
        #pragma unroll
        for (int e = 0; e < 8; ++e) {
            bool sel = x[j*8+e] > thr;
            unsigned bm = __ballot_sync(0xffffffffu, sel);
            if (sel) {
                int pos = base + __popc(bm & ((1u << lane) - 1u));
                pi[pos] = (uint16_t)((((j << 5) + lane) << 3) + e);
            }
            base += __popc(bm);
        }
    if (lane == 0) {
        g_count[row] = base;
        g_mt[row]    = make_float2(m, tau);
    }
}

// ---------------------------------------------------------------------------
// Kernel 3: exact refine + sparse PV (round-13 version, measured 82.4us),
// warp per row, candidate indices staged in smem, coalesced grouped dots,
// warm-started exact Newton, exact fp32 sparse PV.
// ---------------------------------------------------------------------------
__global__ void __launch_bounds__(256) refine_pv_kernel(const float* __restrict__ q,
                                                        const float* __restrict__ k,
                                                        const float* __restrict__ v,
                                                        const int*   __restrict__ mask,
                                                        float* __restrict__ out) {
    __shared__ float    xs  [8][1024];
    __shared__ uint16_t sidx[8][1024];

    const int lane = threadIdx.x & 31;
    const int wid  = threadIdx.x >> 5;
    const size_t row = (size_t)blockIdx.x * 8 + wid;
    const int bh = (int)(row >> 10);
    const int b  = bh >> 3;
    const float scale = 0.08838834764831845f;

    const int sub = lane & 7;
    const int grp = lane >> 3;

    const float4* q4 = (const float4*)(q + row * D_);
    float4 qreg[4];
    #pragma unroll
    for (int r = 0; r < 4; ++r) qreg[r] = q4[sub + 8 * r];

    const int cnt = g_count[row];
    const uint16_t* pi = g_pidx + (row << 10);
    const float2 mt = g_mt[row];
    const float4* kb = (const float4*)(k + (size_t)bh * S_ * D_);
    const int* mrow = mask + ((size_t)b * S_ + (row & 1023)) * S_;

    for (int c = lane; c < cnt; c += 32) sidx[wid][c] = pi[c];
    __syncwarp();

    // 1) exact scores: 4 candidates per pass, 8 lanes each (coalesced K reads)
    for (int cg = 0; cg < cnt; cg += 4) {
        int c = cg + grp;
        int cc = (c < cnt) ? c : (cnt - 1);
        int ki = sidx[wid][cc];
        float s = 0.0f;
        #pragma unroll
        for (int r = 0; r < 4; ++r) {
            float4 kv = kb[(size_t)ki * 32 + sub + 8 * r];
            s = fmaf(qreg[r].x, kv.x, s);
            s = fmaf(qreg[r].y, kv.y, s);
            s = fmaf(qreg[r].z, kv.z, s);
            s = fmaf(qreg[r].w, kv.w, s);
        }
        #pragma unroll
        for (int o = 4; o; o >>= 1) s += __shfl_xor_sync(0xffffffffu, s, o);
        if (c < cnt && sub == 0)
            xs[wid][c] = mrow[ki] ? s * scale : NEG_INF_F;
    }
    __syncwarp();

    // 2) exact rowmax over candidates
    float m = -3.4e38f;
    for (int c = lane; c < cnt; c += 32) m = fmaxf(m, xs[wid][c]);
    #pragma unroll
    for (int o = 16; o; o >>= 1) m = fmaxf(m, __shfl_xor_sync(0xffffffffu, m, o));
    for (int c = lane; c < cnt; c += 32) xs[wid][c] = (xs[wid][c] - m) * 0.5f;
    __syncwarp();

    // 3) exact Newton, warm-started below the root
    float tau = fminf(mt.y + (mt.x - m) * 0.5f - 0.05f, -0.03125f);
    for (int it = 0; it < 10; ++it) {
        float s1 = 0.0f, s2 = 0.0f;
        for (int c = lane; c < cnt; c += 32) {
            float t = fmaxf(xs[wid][c] - tau, 0.0f);
            s1 += t;
            s2 = fmaf(t, t, s2);
        }
        #pragma unroll
        for (int o = 16; o; o >>= 1) {
            s1 += __shfl_xor_sync(0xffffffffu, s1, o);
            s2 += __shfl_xor_sync(0xffffffffu, s2, o);
        }
        tau += (s2 - 1.0f) / (2.0f * s1);
        tau  = fminf(tau, -0.03125f);
        if (fabsf(s2 - 1.0f) < 2e-6f) break;
    }

    // 4) sparse PV: lane owns dims [lane*4, lane*4+4), coalesced V reads
    const float* vg = v + (size_t)bh * S_ * D_ + (lane << 2);
    float4 acc = make_float4(0.f, 0.f, 0.f, 0.f);
    for (int c = 0; c < cnt; ++c) {
        float t = xs[wid][c] - tau;
        if (t > 0.0f) {
            float p = t * t;
            float4 vv = *(const float4*)(vg + (size_t)sidx[wid][c] * D_);
            acc.x = fmaf(p, vv.x, acc.x); acc.y = fmaf(p, vv.y, acc.y);
            acc.z = fmaf(p, vv.z, acc.z); acc.w = fmaf(p, vv.w, acc.w);
        }
    }
    *(float4*)(out + row * D_ + (lane << 2)) = acc;
}

// ---------------------------------------------------------------------------
extern "C" void kernel_launch(void* const* d_in, const int* in_sizes, int n_in,
                              void* d_out, int out_size) {
    (void)in_sizes; (void)n_in; (void)out_size;
    const float* q    = (const float*)d_in[0];
    const float* k    = (const float*)d_in[1];
    const float* v    = (const float*)d_in[2];
    const int*   mask = (const int*)d_in[3];
    float*       out  = (float*)d_out;

    constexpr int QK_SMEM = 30720;
    cudaFuncSetAttribute(qk_kernel, cudaFuncAttributeMaxDynamicSharedMemorySize, QK_SMEM);

    qk_kernel<<<dim3(16, 8, BH_), 256, QK_SMEM>>>(q, k, mask);
    entmax_kernel<<<BH_ * S_ / 16, 512>>>();
    refine_pv_kernel<<<BH_ * S_ / 8, 256>>>(q, k, v, mask, out);
}

// round 15
// speedup vs baseline: 1.1504x; 1.1504x over previous
#include <cuda_runtime.h>
#include <cuda_bf16.h>
#include <cstdint>

#define NEG_INF_F (-1.0e12f)

constexpr int S_  = 1024;
constexpr int D_  = 128;
constexpr int BH_ = 32;   // B*H

// Approx scores (bf16) — the ONLY global scratch now.
static __device__ __align__(16) __nv_bfloat16 g_scores[(size_t)BH_ * S_ * S_];

// ---------------------------------------------------------------------------
// PTX helpers
// ---------------------------------------------------------------------------
__device__ __forceinline__ void ldsm4(uint32_t* r, uint32_t addr) {
    asm volatile("ldmatrix.sync.aligned.m8n8.x4.shared.b16 {%0,%1,%2,%3}, [%4];\n"
                 : "=r"(r[0]), "=r"(r[1]), "=r"(r[2]), "=r"(r[3]) : "r"(addr));
}
__device__ __forceinline__ void mma_bf16(float* c, const uint32_t* a,
                                         uint32_t b0, uint32_t b1) {
    asm volatile("mma.sync.aligned.m16n8k16.row.col.f32.bf16.bf16.f32 "
                 "{%0,%1,%2,%3}, {%4,%5,%6,%7}, {%8,%9}, {%0,%1,%2,%3};\n"
                 : "+f"(c[0]), "+f"(c[1]), "+f"(c[2]), "+f"(c[3])
                 : "r"(a[0]), "r"(a[1]), "r"(a[2]), "r"(a[3]), "r"(b0), "r"(b1));
}
__device__ __forceinline__ uint32_t cvt2(float a, float b) {
    __nv_bfloat162 h = __floats2bfloat162_rn(a, b);
    return *(uint32_t*)&h;
}

// ---------------------------------------------------------------------------
// Kernel 1: approx scores (bf16) = mask ? scale * Q K^T : -1e12
// (round-12/14 version, measured 80.4us — unchanged)
// ---------------------------------------------------------------------------
__global__ void __launch_bounds__(256, 2) qk_kernel(const float* __restrict__ q,
                                                    const float* __restrict__ k,
                                                    const int*   __restrict__ mask) {
    extern __shared__ __align__(16) uint8_t sm[];
    constexpr uint32_t QH = 0, KH = 5120, BUF = 15360;
    const uint32_t sb = (uint32_t)__cvta_generic_to_shared(sm);

    const int tid  = threadIdx.x;
    const int lane = tid & 31;
    const int wid  = tid >> 5;
    const int wm   = wid & 1;
    const int wn   = wid >> 1;
    const int bh   = blockIdx.z;
    const int b    = bh >> 3;
    const int row0 = blockIdx.x << 6;
    const int col0 = blockIdx.y << 7;

    const int pr = tid >> 3;
    const int pc = (tid & 7) << 2;
    const float* qp0 = q + ((size_t)bh * S_ + row0 + pr) * D_ + pc;
    const float* qp1 = qp0 + (size_t)32 * D_;
    const float* kp  = k + ((size_t)bh * S_ + col0 + pr) * D_ + pc;

    float4 Qr[2][2], Kr[2][4];

    auto load_chunk = [&](int c, int s) {
        Qr[s][0] = *(const float4*)(qp0 + c * 32);
        Qr[s][1] = *(const float4*)(qp1 + c * 32);
        #pragma unroll
        for (int i = 0; i < 4; ++i)
            Kr[s][i] = *(const float4*)(kp + (size_t)(32 * i) * D_ + c * 32);
    };
    auto store_chunk = [&](int s, int buf) {
        uint8_t* B = sm + (uint32_t)buf * BUF;
        #pragma unroll
        for (int i = 0; i < 2; ++i) {
            float4 vq = Qr[s][i];
            uint32_t off = 2u * ((uint32_t)(pr + 32 * i) * 40 + pc);
            *(uint2*)(B + QH + off) = make_uint2(cvt2(vq.x, vq.y), cvt2(vq.z, vq.w));
        }
        #pragma unroll
        for (int i = 0; i < 4; ++i) {
            float4 vk = Kr[s][i];
            uint32_t off = 2u * ((uint32_t)(pr + 32 * i) * 40 + pc);
            *(uint2*)(B + KH + off) = make_uint2(cvt2(vk.x, vk.y), cvt2(vk.z, vk.w));
        }
    };

    const int lrA = lane & 15, lcA = (lane >> 4) << 3;
    const int lrB = ((lane >> 4) << 3) + (lane & 7), lcB = ((lane >> 3) & 1) << 3;
    uint32_t aAddr[2], bAddr[2];
    #pragma unroll
    for (int mi = 0; mi < 2; ++mi)
        aAddr[mi] = sb + QH + 2u * ((uint32_t)(wm * 32 + mi * 16 + lrA) * 40 + lcA);
    #pragma unroll
    for (int nt = 0; nt < 2; ++nt)
        bAddr[nt] = sb + KH + 2u * ((uint32_t)(wn * 32 + nt * 16 + lrB) * 40 + lcB);

    load_chunk(0, 0);
    store_chunk(0, 0);
    load_chunk(1, 1);
    __syncthreads();

    float acc[2][4][4] = {};
    constexpr int NC = D_ / 32;

    #pragma unroll
    for (int c = 0; c < NC; ++c) {
        const int buf = c & 1;
        if (c + 2 < NC) load_chunk(c + 2, buf);

        const uint32_t bo = (uint32_t)buf * BUF;
        #pragma unroll
        for (int kk = 0; kk < 2; ++kk) {
            const uint32_t ko = 32u * kk;
            uint32_t Ah[2][4], Bh[2][4];
            ldsm4(Ah[0], aAddr[0] + bo + ko);
            ldsm4(Ah[1], aAddr[1] + bo + ko);
            ldsm4(Bh[0], bAddr[0] + bo + ko);
            ldsm4(Bh[1], bAddr[1] + bo + ko);
            #pragma unroll
            for (int mi = 0; mi < 2; ++mi)
                #pragma unroll
                for (int ni = 0; ni < 4; ++ni)
                    mma_bf16(acc[mi][ni], Ah[mi],
                             Bh[ni >> 1][(ni & 1) * 2], Bh[ni >> 1][(ni & 1) * 2 + 1]);
        }

        if (c + 1 < NC) store_chunk((c + 1) & 1, (c + 1) & 1);
        __syncthreads();
    }

    const float scale = 0.08838834764831845f;
    __nv_bfloat16* srow = g_scores + (size_t)bh * S_ * S_;
    const int*     mrow = mask     + (size_t)b  * S_ * S_;
    const int      rb   = row0 + wm * 32 + (lane >> 2);
    const int      cb   = col0 + wn * 32 + ((lane & 3) << 1);

    #pragma unroll
    for (int mi = 0; mi < 2; ++mi)
        #pragma unroll
        for (int h = 0; h < 2; ++h) {
            int r = rb + mi * 16 + h * 8;
            #pragma unroll
            for (int ni = 0; ni < 4; ++ni) {
                int cc = cb + ni * 8;
                int2 mk = *(const int2*)(mrow + (size_t)r * S_ + cc);
                float f0 = mk.x ? acc[mi][ni][2 * h]     * scale : NEG_INF_F;
                float f1 = mk.y ? acc[mi][ni][2 * h + 1] * scale : NEG_INF_F;
                *(__nv_bfloat162*)(srow + (size_t)r * S_ + cc) =
                    __floats2bfloat162_rn(f0, f1);
            }
        }
}

// ---------------------------------------------------------------------------
// Kernel 2 (FUSED select + refine), one warp per row:
//  1) load 1024 bf16 scores -> regs, rowmax
//  2) PRE-COMPACT x > -1.02 into smem (provable superset: tau >= -1 always,
//     approx error << 0.02) — Newton then runs over ~60 elems, not 1024
//  3) approx Newton for tau over compacted set
//  4) final margin filter (tau - 0.1) compacts indices in place
//  5) exact fp32 q.k for final candidates (8 lanes/candidate, coalesced)
//  6) exact rowmax + warm-started exact Newton + exact sparse PV
// ---------------------------------------------------------------------------
__global__ void __launch_bounds__(256) select_refine_kernel(
        const float* __restrict__ q, const float* __restrict__ k,
        const float* __restrict__ v, const int* __restrict__ mask,
        float* __restrict__ out) {
    __shared__ float    xs  [8][1024];
    __shared__ uint16_t sidx[8][1024];

    const int lane = threadIdx.x & 31;
    const int wid  = threadIdx.x >> 5;
    const size_t row = (size_t)blockIdx.x * 8 + wid;
    const int bh = (int)(row >> 10);
    const int b  = bh >> 3;
    const float scale = 0.08838834764831845f;

    // ---- 1) load approx scores, rowmax
    const uint4* rowp = (const uint4*)(g_scores + row * S_);
    float x[32];
    float ma = -3.4e38f;
    #pragma unroll
    for (int j = 0; j < 4; ++j) {
        uint4 w = rowp[(j << 5) + lane];
        float2 f0 = __bfloat1622float2(*(__nv_bfloat162*)&w.x);
        float2 f1 = __bfloat1622float2(*(__nv_bfloat162*)&w.y);
        float2 f2 = __bfloat1622float2(*(__nv_bfloat162*)&w.z);
        float2 f3 = __bfloat1622float2(*(__nv_bfloat162*)&w.w);
        x[j*8+0] = f0.x; x[j*8+1] = f0.y; x[j*8+2] = f1.x; x[j*8+3] = f1.y;
        x[j*8+4] = f2.x; x[j*8+5] = f2.y; x[j*8+6] = f3.x; x[j*8+7] = f3.y;
        #pragma unroll
        for (int e = 0; e < 8; ++e) ma = fmaxf(ma, x[j*8+e]);
    }
    #pragma unroll
    for (int o = 16; o; o >>= 1) ma = fmaxf(ma, __shfl_xor_sync(0xffffffffu, ma, o));

    #pragma unroll
    for (int e = 0; e < 32; ++e) x[e] = (x[e] - ma) * 0.5f;

    // ---- 2) pre-compact x > -1.02 (superset of support, since tau >= -1)
    int cnt = 0;
    #pragma unroll
    for (int j = 0; j < 4; ++j)
        #pragma unroll
        for (int e = 0; e < 8; ++e) {
            float xv = x[j*8+e];
            bool sel = xv > -1.02f;
            unsigned bm = __ballot_sync(0xffffffffu, sel);
            if (sel) {
                int pos = cnt + __popc(bm & ((1u << lane) - 1u));
                xs[wid][pos]   = xv;
                sidx[wid][pos] = (uint16_t)((((j << 5) + lane) << 3) + e);
            }
            cnt += __popc(bm);
        }
    __syncwarp();

    // ---- 3) approx Newton for tau over the compacted set
    float tau = -1.0f;
    for (int it = 0; it < 12; ++it) {
        float s1 = 0.0f, s2 = 0.0f;
        for (int c = lane; c < cnt; c += 32) {
            float t = fmaxf(xs[wid][c] - tau, 0.0f);
            s1 += t;
            s2 = fmaf(t, t, s2);
        }
        #pragma unroll
        for (int o = 16; o; o >>= 1) {
            s1 += __shfl_xor_sync(0xffffffffu, s1, o);
            s2 += __shfl_xor_sync(0xffffffffu, s2, o);
        }
        tau += (s2 - 1.0f) / (2.0f * s1);
        tau  = fminf(tau, -0.03125f);
        if (fabsf(s2 - 1.0f) < 1e-4f) break;
    }

    // ---- 4) final filter (margin 0.1 covers bf16 score error), compact in place
    const float thr = tau - 0.1f;
    int cnt2 = 0;
    for (int cg = 0; cg < cnt; cg += 32) {
        int c = cg + lane;
        bool sel = false;
        uint16_t ki = 0;
        if (c < cnt) {
            sel = xs[wid][c] > thr;
            ki  = sidx[wid][c];
        }
        unsigned bm = __ballot_sync(0xffffffffu, sel);   // also orders reads/writes
        if (sel) sidx[wid][cnt2 + __popc(bm & ((1u << lane) - 1u))] = ki;
        cnt2 += __popc(bm);
    }
    __syncwarp();

    // ---- 5) exact fp32 scores for final candidates
    const int sub = lane & 7;
    const int grp = lane >> 3;
    const float4* q4 = (const float4*)(q + row * D_);
    float4 qreg[4];
    #pragma unroll
    for (int r = 0; r < 4; ++r) qreg[r] = q4[sub + 8 * r];

    const float4* kb = (const float4*)(k + (size_t)bh * S_ * D_);
    const int* mrow = mask + ((size_t)b * S_ + (row & 1023)) * S_;

    for (int cg = 0; cg < cnt2; cg += 4) {
        int c = cg + grp;
        int cc = (c < cnt2) ? c : (cnt2 - 1);
        int ki = sidx[wid][cc];
        float s = 0.0f;
        #pragma unroll
        for (int r = 0; r < 4; ++r) {
            float4 kv = kb[(size_t)ki * 32 + sub + 8 * r];
            s = fmaf(qreg[r].x, kv.x, s);
            s = fmaf(qreg[r].y, kv.y, s);
            s = fmaf(qreg[r].z, kv.z, s);
            s = fmaf(qreg[r].w, kv.w, s);
        }
        #pragma unroll
        for (int o = 4; o; o >>= 1) s += __shfl_xor_sync(0xffffffffu, s, o);
        if (c < cnt2 && sub == 0)
            xs[wid][c] = mrow[ki] ? s * scale : NEG_INF_F;
    }
    __syncwarp();

    // ---- 6) exact rowmax + warm-started exact Newton + sparse PV
    float me = -3.4e38f;
    for (int c = lane; c < cnt2; c += 32) me = fmaxf(me, xs[wid][c]);
    #pragma unroll
    for (int o = 16; o; o >>= 1) me = fmaxf(me, __shfl_xor_sync(0xffffffffu, me, o));
    for (int c = lane; c < cnt2; c += 32) xs[wid][c] = (xs[wid][c] - me) * 0.5f;
    __syncwarp();

    float te = fminf(tau + (ma - me) * 0.5f - 0.05f, -0.03125f);
    for (int it = 0; it < 10; ++it) {
        float s1 = 0.0f, s2 = 0.0f;
        for (int c = lane; c < cnt2; c += 32) {
            float t = fmaxf(xs[wid][c] - te, 0.0f);
            s1 += t;
            s2 = fmaf(t, t, s2);
        }
        #pragma unroll
        for (int o = 16; o; o >>= 1) {
            s1 += __shfl_xor_sync(0xffffffffu, s1, o);
            s2 += __shfl_xor_sync(0xffffffffu, s2, o);
        }
        te += (s2 - 1.0f) / (2.0f * s1);
        te  = fminf(te, -0.03125f);
        if (fabsf(s2 - 1.0f) < 2e-6f) break;
    }

    const float* vg = v + (size_t)bh * S_ * D_ + (lane << 2);
    float4 acc = make_float4(0.f, 0.f, 0.f, 0.f);
    for (int c = 0; c < cnt2; ++c) {
        float t = xs[wid][c] - te;
        if (t > 0.0f) {
            float p = t * t;
            float4 vv = *(const float4*)(vg + (size_t)sidx[wid][c] * D_);
            acc.x = fmaf(p, vv.x, acc.x); acc.y = fmaf(p, vv.y, acc.y);
            acc.z = fmaf(p, vv.z, acc.z); acc.w = fmaf(p, vv.w, acc.w);
        }
    }
    *(float4*)(out + row * D_ + (lane << 2)) = acc;
}

// ---------------------------------------------------------------------------
extern "C" void kernel_launch(void* const* d_in, const int* in_sizes, int n_in,
                              void* d_out, int out_size) {
    (void)in_sizes; (void)n_in; (void)out_size;
    const float* q    = (const float*)d_in[0];
    const float* k    = (const float*)d_in[1];
    const float* v    = (const float*)d_in[2];
    const int*   mask = (const int*)d_in[3];
    float*       out  = (float*)d_out;

    constexpr int QK_SMEM = 30720;
    cudaFuncSetAttribute(qk_kernel, cudaFuncAttributeMaxDynamicSharedMemorySize, QK_SMEM);

    qk_kernel<<<dim3(16, 8, BH_), 256, QK_SMEM>>>(q, k, mask);
    select_refine_kernel<<<BH_ * S_ / 8, 256>>>(q, k, v, mask, out);
}

// round 16
// speedup vs baseline: 1.2578x; 1.0934x over previous
#include <cuda_runtime.h>
#include <cuda_bf16.h>
#include <cstdint>

#define NEG_INF_F (-1.0e12f)

constexpr int S_  = 1024;
constexpr int D_  = 128;
constexpr int BH_ = 32;   // B*H

// Approx scores (bf16) — the ONLY global scratch.
static __device__ __align__(16) __nv_bfloat16 g_scores[(size_t)BH_ * S_ * S_];

// ---------------------------------------------------------------------------
// PTX helpers
// ---------------------------------------------------------------------------
__device__ __forceinline__ void ldsm4(uint32_t* r, uint32_t addr) {
    asm volatile("ldmatrix.sync.aligned.m8n8.x4.shared.b16 {%0,%1,%2,%3}, [%4];\n"
                 : "=r"(r[0]), "=r"(r[1]), "=r"(r[2]), "=r"(r[3]) : "r"(addr));
}
__device__ __forceinline__ void mma_bf16(float* c, const uint32_t* a,
                                         uint32_t b0, uint32_t b1) {
    asm volatile("mma.sync.aligned.m16n8k16.row.col.f32.bf16.bf16.f32 "
                 "{%0,%1,%2,%3}, {%4,%5,%6,%7}, {%8,%9}, {%0,%1,%2,%3};\n"
                 : "+f"(c[0]), "+f"(c[1]), "+f"(c[2]), "+f"(c[3])
                 : "r"(a[0]), "r"(a[1]), "r"(a[2]), "r"(a[3]), "r"(b0), "r"(b1));
}
__device__ __forceinline__ uint32_t cvt2(float a, float b) {
    __nv_bfloat162 h = __floats2bfloat162_rn(a, b);
    return *(uint32_t*)&h;
}

// ---------------------------------------------------------------------------
// Kernel 1: approx scores (bf16) = mask ? scale * Q K^T : -1e12
// Mainloop unchanged (measured 80.4us shape). NEW: epilogue stages scaled
// bf16 scores in smem, then a row-per-warp phase does fully coalesced
// mask LDG.128 + LDS.64 + STG.64 (was ~8 wavefronts per instruction).
// ---------------------------------------------------------------------------
__global__ void __launch_bounds__(256, 2) qk_kernel(const float* __restrict__ q,
                                                    const float* __restrict__ k,
                                                    const int*   __restrict__ mask) {
    extern __shared__ __align__(16) uint8_t sm[];
    constexpr uint32_t QH = 0, KH = 5120, BUF = 15360;
    const uint32_t sb = (uint32_t)__cvta_generic_to_shared(sm);

    const int tid  = threadIdx.x;
    const int lane = tid & 31;
    const int wid  = tid >> 5;
    const int wm   = wid & 1;
    const int wn   = wid >> 1;
    const int bh   = blockIdx.z;
    const int b    = bh >> 3;
    const int row0 = blockIdx.x << 6;
    const int col0 = blockIdx.y << 7;

    const int pr = tid >> 3;
    const int pc = (tid & 7) << 2;
    const float* qp0 = q + ((size_t)bh * S_ + row0 + pr) * D_ + pc;
    const float* qp1 = qp0 + (size_t)32 * D_;
    const float* kp  = k + ((size_t)bh * S_ + col0 + pr) * D_ + pc;

    float4 Qr[2][2], Kr[2][4];

    auto load_chunk = [&](int c, int s) {
        Qr[s][0] = *(const float4*)(qp0 + c * 32);
        Qr[s][1] = *(const float4*)(qp1 + c * 32);
        #pragma unroll
        for (int i = 0; i < 4; ++i)
            Kr[s][i] = *(const float4*)(kp + (size_t)(32 * i) * D_ + c * 32);
    };
    auto store_chunk = [&](int s, int buf) {
        uint8_t* B = sm + (uint32_t)buf * BUF;
        #pragma unroll
        for (int i = 0; i < 2; ++i) {
            float4 vq = Qr[s][i];
            uint32_t off = 2u * ((uint32_t)(pr + 32 * i) * 40 + pc);
            *(uint2*)(B + QH + off) = make_uint2(cvt2(vq.x, vq.y), cvt2(vq.z, vq.w));
        }
        #pragma unroll
        for (int i = 0; i < 4; ++i) {
            float4 vk = Kr[s][i];
            uint32_t off = 2u * ((uint32_t)(pr + 32 * i) * 40 + pc);
            *(uint2*)(B + KH + off) = make_uint2(cvt2(vk.x, vk.y), cvt2(vk.z, vk.w));
        }
    };

    const int lrA = lane & 15, lcA = (lane >> 4) << 3;
    const int lrB = ((lane >> 4) << 3) + (lane & 7), lcB = ((lane >> 3) & 1) << 3;
    uint32_t aAddr[2], bAddr[2];
    #pragma unroll
    for (int mi = 0; mi < 2; ++mi)
        aAddr[mi] = sb + QH + 2u * ((uint32_t)(wm * 32 + mi * 16 + lrA) * 40 + lcA);
    #pragma unroll
    for (int nt = 0; nt < 2; ++nt)
        bAddr[nt] = sb + KH + 2u * ((uint32_t)(wn * 32 + nt * 16 + lrB) * 40 + lcB);

    load_chunk(0, 0);
    store_chunk(0, 0);
    load_chunk(1, 1);
    __syncthreads();

    float acc[2][4][4] = {};
    constexpr int NC = D_ / 32;

    #pragma unroll
    for (int c = 0; c < NC; ++c) {
        const int buf = c & 1;
        if (c + 2 < NC) load_chunk(c + 2, buf);

        const uint32_t bo = (uint32_t)buf * BUF;
        #pragma unroll
        for (int kk = 0; kk < 2; ++kk) {
            const uint32_t ko = 32u * kk;
            uint32_t Ah[2][4], Bh[2][4];
            ldsm4(Ah[0], aAddr[0] + bo + ko);
            ldsm4(Ah[1], aAddr[1] + bo + ko);
            ldsm4(Bh[0], bAddr[0] + bo + ko);
            ldsm4(Bh[1], bAddr[1] + bo + ko);
            #pragma unroll
            for (int mi = 0; mi < 2; ++mi)
                #pragma unroll
                for (int ni = 0; ni < 4; ++ni)
                    mma_bf16(acc[mi][ni], Ah[mi],
                             Bh[ni >> 1][(ni & 1) * 2], Bh[ni >> 1][(ni & 1) * 2 + 1]);
        }

        if (c + 1 < NC) store_chunk((c + 1) & 1, (c + 1) & 1);
        __syncthreads();
    }

    // ---- NEW epilogue: stage scaled bf16 scores in smem (pitch 65 uint32)
    const float scale = 0.08838834764831845f;
    uint32_t* st = (uint32_t*)sm;                 // 64 x 65 uint32 = 16640 B
    {
        const int rb = wm * 32 + (lane >> 2);     // local row base
        const int cu = wn * 16 + (lane & 3);      // uint32 col base
        #pragma unroll
        for (int mi = 0; mi < 2; ++mi)
            #pragma unroll
            for (int h = 0; h < 2; ++h) {
                int lr = rb + mi * 16 + h * 8;
                #pragma unroll
                for (int ni = 0; ni < 4; ++ni)
                    st[(uint32_t)lr * 65 + cu + ni * 4] =
                        cvt2(acc[mi][ni][2 * h] * scale, acc[mi][ni][2 * h + 1] * scale);
            }
    }
    __syncthreads();

    // ---- coalesced write phase: warp wid handles rows wid*8..wid*8+7
    const uint32_t NEGB = (uint32_t)__bfloat16_as_ushort(__float2bfloat16_rn(NEG_INF_F));
    #pragma unroll
    for (int rr = 0; rr < 8; ++rr) {
        const int lr = wid * 8 + rr;
        const size_t grow = (size_t)row0 + lr;
        int4 mk = *(const int4*)(mask + ((size_t)b * S_ + grow) * S_ + col0 + (lane << 2));
        uint32_t s0 = st[(uint32_t)lr * 65 + (lane << 1)];
        uint32_t s1 = st[(uint32_t)lr * 65 + (lane << 1) + 1];
        uint32_t o0 = (mk.x ? (s0 & 0xFFFFu) : NEGB) | ((mk.y ? (s0 >> 16) : NEGB) << 16);
        uint32_t o1 = (mk.z ? (s1 & 0xFFFFu) : NEGB) | ((mk.w ? (s1 >> 16) : NEGB) << 16);
        *(uint2*)(g_scores + ((size_t)bh * S_ + grow) * S_ + col0 + (lane << 2)) =
            make_uint2(o0, o1);
    }
}

// ---------------------------------------------------------------------------
// Kernel 2 (fused select + refine), one warp per row.
// NEW: pre-compaction via per-lane count + warp prefix scan (replaces 32
// serialized ballot rounds); branchless PV loop.
// ---------------------------------------------------------------------------
__global__ void __launch_bounds__(256) select_refine_kernel(
        const float* __restrict__ q, const float* __restrict__ k,
        const float* __restrict__ v, const int* __restrict__ mask,
        float* __restrict__ out) {
    __shared__ float    xs  [8][1024];
    __shared__ uint16_t sidx[8][1024];

    const int lane = threadIdx.x & 31;
    const int wid  = threadIdx.x >> 5;
    const size_t row = (size_t)blockIdx.x * 8 + wid;
    const int bh = (int)(row >> 10);
    const int b  = bh >> 3;
    const float scale = 0.08838834764831845f;

    // ---- 1) load approx scores, rowmax
    const uint4* rowp = (const uint4*)(g_scores + row * S_);
    float x[32];
    float ma = -3.4e38f;
    #pragma unroll
    for (int j = 0; j < 4; ++j) {
        uint4 w = rowp[(j << 5) + lane];
        float2 f0 = __bfloat1622float2(*(__nv_bfloat162*)&w.x);
        float2 f1 = __bfloat1622float2(*(__nv_bfloat162*)&w.y);
        float2 f2 = __bfloat1622float2(*(__nv_bfloat162*)&w.z);
        float2 f3 = __bfloat1622float2(*(__nv_bfloat162*)&w.w);
        x[j*8+0] = f0.x; x[j*8+1] = f0.y; x[j*8+2] = f1.x; x[j*8+3] = f1.y;
        x[j*8+4] = f2.x; x[j*8+5] = f2.y; x[j*8+6] = f3.x; x[j*8+7] = f3.y;
        #pragma unroll
        for (int e = 0; e < 8; ++e) ma = fmaxf(ma, x[j*8+e]);
    }
    #pragma unroll
    for (int o = 16; o; o >>= 1) ma = fmaxf(ma, __shfl_xor_sync(0xffffffffu, ma, o));

    #pragma unroll
    for (int e = 0; e < 32; ++e) x[e] = (x[e] - ma) * 0.5f;

    // ---- 2) pre-compact x > -1.02 (superset of support; tau >= -1 always).
    // Per-lane count + warp prefix scan + per-lane contiguous writes.
    int nl = 0;
    #pragma unroll
    for (int e = 0; e < 32; ++e) nl += (x[e] > -1.02f) ? 1 : 0;

    int off = nl;
    #pragma unroll
    for (int o = 1; o < 32; o <<= 1) {
        int t = __shfl_up_sync(0xffffffffu, off, o);
        if (lane >= o) off += t;
    }
    const int cnt = __shfl_sync(0xffffffffu, off, 31);
    off -= nl;   // exclusive offset for this lane

    {
        int p = off;
        #pragma unroll
        for (int j = 0; j < 4; ++j)
            #pragma unroll
            for (int e = 0; e < 8; ++e) {
                float xv = x[j*8+e];
                if (xv > -1.02f) {
                    xs[wid][p]   = xv;
                    sidx[wid][p] = (uint16_t)((((j << 5) + lane) << 3) + e);
                    ++p;
                }
            }
    }
    __syncwarp();

    // ---- 3) approx Newton for tau over the compacted set
    float tau = -1.0f;
    for (int it = 0; it < 12; ++it) {
        float s1 = 0.0f, s2 = 0.0f;
        for (int c = lane; c < cnt; c += 32) {
            float t = fmaxf(xs[wid][c] - tau, 0.0f);
            s1 += t;
            s2 = fmaf(t, t, s2);
        }
        #pragma unroll
        for (int o = 16; o; o >>= 1) {
            s1 += __shfl_xor_sync(0xffffffffu, s1, o);
            s2 += __shfl_xor_sync(0xffffffffu, s2, o);
        }
        tau += (s2 - 1.0f) / (2.0f * s1);
        tau  = fminf(tau, -0.03125f);
        if (fabsf(s2 - 1.0f) < 1e-4f) break;
    }

    // ---- 4) final filter (margin 0.1 covers bf16 score error)
    const float thr = tau - 0.1f;
    int cnt2 = 0;
    for (int cg = 0; cg < cnt; cg += 32) {
        int c = cg + lane;
        bool sel = false;
        uint16_t ki = 0;
        if (c < cnt) {
            sel = xs[wid][c] > thr;
            ki  = sidx[wid][c];
        }
        unsigned bm = __ballot_sync(0xffffffffu, sel);
        if (sel) sidx[wid][cnt2 + __popc(bm & ((1u << lane) - 1u))] = ki;
        cnt2 += __popc(bm);
    }
    __syncwarp();

    // ---- 5) exact fp32 scores for final candidates (8 lanes per candidate)
    const int sub = lane & 7;
    const int grp = lane >> 3;
    const float4* q4 = (const float4*)(q + row * D_);
    float4 qreg[4];
    #pragma unroll
    for (int r = 0; r < 4; ++r) qreg[r] = q4[sub + 8 * r];

    const float4* kb = (const float4*)(k + (size_t)bh * S_ * D_);
    const int* mrow = mask + ((size_t)b * S_ + (row & 1023)) * S_;

    for (int cg = 0; cg < cnt2; cg += 4) {
        int c = cg + grp;
        int cc = (c < cnt2) ? c : (cnt2 - 1);
        int ki = sidx[wid][cc];
        float s = 0.0f;
        #pragma unroll
        for (int r = 0; r < 4; ++r) {
            float4 kv = kb[(size_t)ki * 32 + sub + 8 * r];
            s = fmaf(qreg[r].x, kv.x, s);
            s = fmaf(qreg[r].y, kv.y, s);
            s = fmaf(qreg[r].z, kv.z, s);
            s = fmaf(qreg[r].w, kv.w, s);
        }
        #pragma unroll
        for (int o = 4; o; o >>= 1) s += __shfl_xor_sync(0xffffffffu, s, o);
        if (c < cnt2 && sub == 0)
            xs[wid][c] = mrow[ki] ? s * scale : NEG_INF_F;
    }
    __syncwarp();

    // ---- 6) exact rowmax + warm-started exact Newton + branchless sparse PV
    float me = -3.4e38f;
    for (int c = lane; c < cnt2; c += 32) me = fmaxf(me, xs[wid][c]);
    #pragma unroll
    for (int o = 16; o; o >>= 1) me = fmaxf(me, __shfl_xor_sync(0xffffffffu, me, o));
    for (int c = lane; c < cnt2; c += 32) xs[wid][c] = (xs[wid][c] - me) * 0.5f;
    __syncwarp();

    float te = fminf(tau + (ma - me) * 0.5f - 0.05f, -0.03125f);
    for (int it = 0; it < 10; ++it) {
        float s1 = 0.0f, s2 = 0.0f;
        for (int c = lane; c < cnt2; c += 32) {
            float t = fmaxf(xs[wid][c] - te, 0.0f);
            s1 += t;
            s2 = fmaf(t, t, s2);
        }
        #pragma unroll
        for (int o = 16; o; o >>= 1) {
            s1 += __shfl_xor_sync(0xffffffffu, s1, o);
            s2 += __shfl_xor_sync(0xffffffffu, s2, o);
        }
        te += (s2 - 1.0f) / (2.0f * s1);
        te  = fminf(te, -0.03125f);
        if (fabsf(s2 - 1.0f) < 2e-6f) break;
    }

    const float* vg = v + (size_t)bh * S_ * D_ + (lane << 2);
    float4 acc = make_float4(0.f, 0.f, 0.f, 0.f);
    for (int c = 0; c < cnt2; ++c) {              // branchless: p=0 terms are no-ops
        float t = fmaxf(xs[wid][c] - te, 0.0f);
        float p = t * t;
        float4 vv = *(const float4*)(vg + (size_t)sidx[wid][c] * D_);
        acc.x = fmaf(p, vv.x, acc.x); acc.y = fmaf(p, vv.y, acc.y);
        acc.z = fmaf(p, vv.z, acc.z); acc.w = fmaf(p, vv.w, acc.w);
    }
    *(float4*)(out + row * D_ + (lane << 2)) = acc;
}

// ---------------------------------------------------------------------------
extern "C" void kernel_launch(void* const* d_in, const int* in_sizes, int n_in,
                              void* d_out, int out_size) {
    (void)in_sizes; (void)n_in; (void)out_size;
    const float* q    = (const float*)d_in[0];
    const float* k    = (const float*)d_in[1];
    const float* v    = (const float*)d_in[2];
    const int*   mask = (const int*)d_in[3];
    float*       out  = (float*)d_out;

    constexpr int QK_SMEM = 30720;
    cudaFuncSetAttribute(qk_kernel, cudaFuncAttributeMaxDynamicSharedMemorySize, QK_SMEM);

    qk_kernel<<<dim3(16, 8, BH_), 256, QK_SMEM>>>(q, k, mask);
    select_refine_kernel<<<BH_ * S_ / 8, 256>>>(q, k, v, mask, out);
}

// round 17
// speedup vs baseline: 1.3351x; 1.0615x over previous
#include <cuda_runtime.h>
#include <cuda_bf16.h>
#include <cstdint>

#define NEG_INF_F (-1.0e12f)

constexpr int S_  = 1024;
constexpr int D_  = 128;
constexpr int BH_ = 32;   // B*H

// Approx scores (bf16) — the ONLY global scratch.
static __device__ __align__(16) __nv_bfloat16 g_scores[(size_t)BH_ * S_ * S_];

// ---------------------------------------------------------------------------
// PTX helpers
// ---------------------------------------------------------------------------
__device__ __forceinline__ void ldsm4(uint32_t* r, uint32_t addr) {
    asm volatile("ldmatrix.sync.aligned.m8n8.x4.shared.b16 {%0,%1,%2,%3}, [%4];\n"
                 : "=r"(r[0]), "=r"(r[1]), "=r"(r[2]), "=r"(r[3]) : "r"(addr));
}
__device__ __forceinline__ void mma_bf16(float* c, const uint32_t* a,
                                         uint32_t b0, uint32_t b1) {
    asm volatile("mma.sync.aligned.m16n8k16.row.col.f32.bf16.bf16.f32 "
                 "{%0,%1,%2,%3}, {%4,%5,%6,%7}, {%8,%9}, {%0,%1,%2,%3};\n"
                 : "+f"(c[0]), "+f"(c[1]), "+f"(c[2]), "+f"(c[3])
                 : "r"(a[0]), "r"(a[1]), "r"(a[2]), "r"(a[3]), "r"(b0), "r"(b1));
}
__device__ __forceinline__ uint32_t cvt2(float a, float b) {
    __nv_bfloat162 h = __floats2bfloat162_rn(a, b);
    return *(uint32_t*)&h;
}

// ---------------------------------------------------------------------------
// Kernel 1: approx scores (bf16) = mask ? scale * Q K^T : -1e12
// (round-16 version with coalesced smem-staged epilogue, measured ~61us)
// ---------------------------------------------------------------------------
__global__ void __launch_bounds__(256, 2) qk_kernel(const float* __restrict__ q,
                                                    const float* __restrict__ k,
                                                    const int*   __restrict__ mask) {
    extern __shared__ __align__(16) uint8_t sm[];
    constexpr uint32_t QH = 0, KH = 5120, BUF = 15360;
    const uint32_t sb = (uint32_t)__cvta_generic_to_shared(sm);

    const int tid  = threadIdx.x;
    const int lane = tid & 31;
    const int wid  = tid >> 5;
    const int wm   = wid & 1;
    const int wn   = wid >> 1;
    const int bh   = blockIdx.z;
    const int b    = bh >> 3;
    const int row0 = blockIdx.x << 6;
    const int col0 = blockIdx.y << 7;

    const int pr = tid >> 3;
    const int pc = (tid & 7) << 2;
    const float* qp0 = q + ((size_t)bh * S_ + row0 + pr) * D_ + pc;
    const float* qp1 = qp0 + (size_t)32 * D_;
    const float* kp  = k + ((size_t)bh * S_ + col0 + pr) * D_ + pc;

    float4 Qr[2][2], Kr[2][4];

    auto load_chunk = [&](int c, int s) {
        Qr[s][0] = *(const float4*)(qp0 + c * 32);
        Qr[s][1] = *(const float4*)(qp1 + c * 32);
        #pragma unroll
        for (int i = 0; i < 4; ++i)
            Kr[s][i] = *(const float4*)(kp + (size_t)(32 * i) * D_ + c * 32);
    };
    auto store_chunk = [&](int s, int buf) {
        uint8_t* B = sm + (uint32_t)buf * BUF;
        #pragma unroll
        for (int i = 0; i < 2; ++i) {
            float4 vq = Qr[s][i];
            uint32_t off = 2u * ((uint32_t)(pr + 32 * i) * 40 + pc);
            *(uint2*)(B + QH + off) = make_uint2(cvt2(vq.x, vq.y), cvt2(vq.z, vq.w));
        }
        #pragma unroll
        for (int i = 0; i < 4; ++i) {
            float4 vk = Kr[s][i];
            uint32_t off = 2u * ((uint32_t)(pr + 32 * i) * 40 + pc);
            *(uint2*)(B + KH + off) = make_uint2(cvt2(vk.x, vk.y), cvt2(vk.z, vk.w));
        }
    };

    const int lrA = lane & 15, lcA = (lane >> 4) << 3;
    const int lrB = ((lane >> 4) << 3) + (lane & 7), lcB = ((lane >> 3) & 1) << 3;
    uint32_t aAddr[2], bAddr[2];
    #pragma unroll
    for (int mi = 0; mi < 2; ++mi)
        aAddr[mi] = sb + QH + 2u * ((uint32_t)(wm * 32 + mi * 16 + lrA) * 40 + lcA);
    #pragma unroll
    for (int nt = 0; nt < 2; ++nt)
        bAddr[nt] = sb + KH + 2u * ((uint32_t)(wn * 32 + nt * 16 + lrB) * 40 + lcB);

    load_chunk(0, 0);
    store_chunk(0, 0);
    load_chunk(1, 1);
    __syncthreads();

    float acc[2][4][4] = {};
    constexpr int NC = D_ / 32;

    #pragma unroll
    for (int c = 0; c < NC; ++c) {
        const int buf = c & 1;
        if (c + 2 < NC) load_chunk(c + 2, buf);

        const uint32_t bo = (uint32_t)buf * BUF;
        #pragma unroll
        for (int kk = 0; kk < 2; ++kk) {
            const uint32_t ko = 32u * kk;
            uint32_t Ah[2][4], Bh[2][4];
            ldsm4(Ah[0], aAddr[0] + bo + ko);
            ldsm4(Ah[1], aAddr[1] + bo + ko);
            ldsm4(Bh[0], bAddr[0] + bo + ko);
            ldsm4(Bh[1], bAddr[1] + bo + ko);
            #pragma unroll
            for (int mi = 0; mi < 2; ++mi)
                #pragma unroll
                for (int ni = 0; ni < 4; ++ni)
                    mma_bf16(acc[mi][ni], Ah[mi],
                             Bh[ni >> 1][(ni & 1) * 2], Bh[ni >> 1][(ni & 1) * 2 + 1]);
        }

        if (c + 1 < NC) store_chunk((c + 1) & 1, (c + 1) & 1);
        __syncthreads();
    }

    // ---- epilogue: stage scaled bf16 scores in smem (pitch 65 uint32)
    const float scale = 0.08838834764831845f;
    uint32_t* st = (uint32_t*)sm;
    {
        const int rb = wm * 32 + (lane >> 2);
        const int cu = wn * 16 + (lane & 3);
        #pragma unroll
        for (int mi = 0; mi < 2; ++mi)
            #pragma unroll
            for (int h = 0; h < 2; ++h) {
                int lr = rb + mi * 16 + h * 8;
                #pragma unroll
                for (int ni = 0; ni < 4; ++ni)
                    st[(uint32_t)lr * 65 + cu + ni * 4] =
                        cvt2(acc[mi][ni][2 * h] * scale, acc[mi][ni][2 * h + 1] * scale);
            }
    }
    __syncthreads();

    const uint32_t NEGB = (uint32_t)__bfloat16_as_ushort(__float2bfloat16_rn(NEG_INF_F));
    #pragma unroll
    for (int rr = 0; rr < 8; ++rr) {
        const int lr = wid * 8 + rr;
        const size_t grow = (size_t)row0 + lr;
        int4 mk = *(const int4*)(mask + ((size_t)b * S_ + grow) * S_ + col0 + (lane << 2));
        uint32_t s0 = st[(uint32_t)lr * 65 + (lane << 1)];
        uint32_t s1 = st[(uint32_t)lr * 65 + (lane << 1) + 1];
        uint32_t o0 = (mk.x ? (s0 & 0xFFFFu) : NEGB) | ((mk.y ? (s0 >> 16) : NEGB) << 16);
        uint32_t o1 = (mk.z ? (s1 & 0xFFFFu) : NEGB) | ((mk.w ? (s1 >> 16) : NEGB) << 16);
        *(uint2*)(g_scores + ((size_t)bh * S_ + grow) * S_ + col0 + (lane << 2)) =
            make_uint2(o0, o1);
    }
}

// ---------------------------------------------------------------------------
// Kernel 2 (fused select + refine), one warp per row. Round-17 trims:
// raw-score pre-compact threshold, approx Newton tol 5e-3 (8 iters),
// margin 0.05 (covers <=0.009 worst-case x error + tau slack), exact
// Newton tol 1e-5 (8 iters), PV unrolled x2.
// ---------------------------------------------------------------------------
__global__ void __launch_bounds__(256) select_refine_kernel(
        const float* __restrict__ q, const float* __restrict__ k,
        const float* __restrict__ v, const int* __restrict__ mask,
        float* __restrict__ out) {
    __shared__ float    xs  [8][1024];
    __shared__ uint16_t sidx[8][1024];

    const int lane = threadIdx.x & 31;
    const int wid  = threadIdx.x >> 5;
    const size_t row = (size_t)blockIdx.x * 8 + wid;
    const int bh = (int)(row >> 10);
    const int b  = bh >> 3;
    const float scale = 0.08838834764831845f;

    // ---- 1) load approx scores (raw s, bf16->fp32), rowmax
    const uint4* rowp = (const uint4*)(g_scores + row * S_);
    float x[32];
    float ma = -3.4e38f;
    #pragma unroll
    for (int j = 0; j < 4; ++j) {
        uint4 w = rowp[(j << 5) + lane];
        float2 f0 = __bfloat1622float2(*(__nv_bfloat162*)&w.x);
        float2 f1 = __bfloat1622float2(*(__nv_bfloat162*)&w.y);
        float2 f2 = __bfloat1622float2(*(__nv_bfloat162*)&w.z);
        float2 f3 = __bfloat1622float2(*(__nv_bfloat162*)&w.w);
        x[j*8+0] = f0.x; x[j*8+1] = f0.y; x[j*8+2] = f1.x; x[j*8+3] = f1.y;
        x[j*8+4] = f2.x; x[j*8+5] = f2.y; x[j*8+6] = f3.x; x[j*8+7] = f3.y;
        #pragma unroll
        for (int e = 0; e < 8; ++e) ma = fmaxf(ma, x[j*8+e]);
    }
    #pragma unroll
    for (int o = 16; o; o >>= 1) ma = fmaxf(ma, __shfl_xor_sync(0xffffffffu, ma, o));

    // ---- 2) pre-compact raw s > ma - 2.04  (== x > -1.02; tau >= -1 always)
    const float thr0 = ma - 2.04f;
    int nl = 0;
    #pragma unroll
    for (int e = 0; e < 32; ++e) nl += (x[e] > thr0) ? 1 : 0;

    int off = nl;
    #pragma unroll
    for (int o = 1; o < 32; o <<= 1) {
        int t = __shfl_up_sync(0xffffffffu, off, o);
        if (lane >= o) off += t;
    }
    const int cnt = __shfl_sync(0xffffffffu, off, 31);
    off -= nl;

    {
        int p = off;
        #pragma unroll
        for (int j = 0; j < 4; ++j)
            #pragma unroll
            for (int e = 0; e < 8; ++e) {
                float sv = x[j*8+e];
                if (sv > thr0) {
                    xs[wid][p]   = (sv - ma) * 0.5f;     // normalize only selected
                    sidx[wid][p] = (uint16_t)((((j << 5) + lane) << 3) + e);
                    ++p;
                }
            }
    }
    __syncwarp();

    // ---- 3) approx Newton (tol 5e-3 -> tau slack <= 0.0025, inside margin)
    float tau = -1.0f;
    for (int it = 0; it < 8; ++it) {
        float s1 = 0.0f, s2 = 0.0f;
        for (int c = lane; c < cnt; c += 32) {
            float t = fmaxf(xs[wid][c] - tau, 0.0f);
            s1 += t;
            s2 = fmaf(t, t, s2);
        }
        #pragma unroll
        for (int o = 16; o; o >>= 1) {
            s1 += __shfl_xor_sync(0xffffffffu, s1, o);
            s2 += __shfl_xor_sync(0xffffffffu, s2, o);
        }
        tau += (s2 - 1.0f) / (2.0f * s1);
        tau  = fminf(tau, -0.03125f);
        if (fabsf(s2 - 1.0f) < 5e-3f) break;
    }

    // ---- 4) final filter, margin 0.05 (worst-case x error ~0.009)
    const float thr = tau - 0.05f;
    int cnt2 = 0;
    for (int cg = 0; cg < cnt; cg += 32) {
        int c = cg + lane;
        bool sel = false;
        uint16_t ki = 0;
        if (c < cnt) {
            sel = xs[wid][c] > thr;
            ki  = sidx[wid][c];
        }
        unsigned bm = __ballot_sync(0xffffffffu, sel);
        if (sel) sidx[wid][cnt2 + __popc(bm & ((1u << lane) - 1u))] = ki;
        cnt2 += __popc(bm);
    }
    __syncwarp();

    // ---- 5) exact fp32 scores for final candidates (8 lanes per candidate)
    const int sub = lane & 7;
    const int grp = lane >> 3;
    const float4* q4 = (const float4*)(q + row * D_);
    float4 qreg[4];
    #pragma unroll
    for (int r = 0; r < 4; ++r) qreg[r] = q4[sub + 8 * r];

    const float4* kb = (const float4*)(k + (size_t)bh * S_ * D_);
    const int* mrow = mask + ((size_t)b * S_ + (row & 1023)) * S_;

    for (int cg = 0; cg < cnt2; cg += 4) {
        int c = cg + grp;
        int cc = (c < cnt2) ? c : (cnt2 - 1);
        int ki = sidx[wid][cc];
        float s = 0.0f;
        #pragma unroll
        for (int r = 0; r < 4; ++r) {
            float4 kv = kb[(size_t)ki * 32 + sub + 8 * r];
            s = fmaf(qreg[r].x, kv.x, s);
            s = fmaf(qreg[r].y, kv.y, s);
            s = fmaf(qreg[r].z, kv.z, s);
            s = fmaf(qreg[r].w, kv.w, s);
        }
        #pragma unroll
        for (int o = 4; o; o >>= 1) s += __shfl_xor_sync(0xffffffffu, s, o);
        if (c < cnt2 && sub == 0)
            xs[wid][c] = mrow[ki] ? s * scale : NEG_INF_F;
    }
    __syncwarp();

    // ---- 6) exact rowmax + warm-started exact Newton + unrolled sparse PV
    float me = -3.4e38f;
    for (int c = lane; c < cnt2; c += 32) me = fmaxf(me, xs[wid][c]);
    #pragma unroll
    for (int o = 16; o; o >>= 1) me = fmaxf(me, __shfl_xor_sync(0xffffffffu, me, o));
    for (int c = lane; c < cnt2; c += 32) xs[wid][c] = (xs[wid][c] - me) * 0.5f;
    __syncwarp();

    // warm start: approx->exact tau shift <= score err (0.009) + approx slack
    float te = fminf(tau + (ma - me) * 0.5f - 0.03f, -0.03125f);
    for (int it = 0; it < 8; ++it) {
        float s1 = 0.0f, s2 = 0.0f;
        for (int c = lane; c < cnt2; c += 32) {
            float t = fmaxf(xs[wid][c] - te, 0.0f);
            s1 += t;
            s2 = fmaf(t, t, s2);
        }
        #pragma unroll
        for (int o = 16; o; o >>= 1) {
            s1 += __shfl_xor_sync(0xffffffffu, s1, o);
            s2 += __shfl_xor_sync(0xffffffffu, s2, o);
        }
        te += (s2 - 1.0f) / (2.0f * s1);
        te  = fminf(te, -0.03125f);
        if (fabsf(s2 - 1.0f) < 1e-5f) break;
    }

    const float* vg = v + (size_t)bh * S_ * D_ + (lane << 2);
    float4 acc = make_float4(0.f, 0.f, 0.f, 0.f);
    int c = 0;
    for (; c + 2 <= cnt2; c += 2) {               // unroll x2, branchless
        float t0 = fmaxf(xs[wid][c]     - te, 0.0f);
        float t1 = fmaxf(xs[wid][c + 1] - te, 0.0f);
        float p0 = t0 * t0, p1 = t1 * t1;
        float4 v0 = *(const float4*)(vg + (size_t)sidx[wid][c]     * D_);
        float4 v1 = *(const float4*)(vg + (size_t)sidx[wid][c + 1] * D_);
        acc.x = fmaf(p0, v0.x, acc.x); acc.y = fmaf(p0, v0.y, acc.y);
        acc.z = fmaf(p0, v0.z, acc.z); acc.w = fmaf(p0, v0.w, acc.w);
        acc.x = fmaf(p1, v1.x, acc.x); acc.y = fmaf(p1, v1.y, acc.y);
        acc.z = fmaf(p1, v1.z, acc.z); acc.w = fmaf(p1, v1.w, acc.w);
    }
    for (; c < cnt2; ++c) {
        float t = fmaxf(xs[wid][c] - te, 0.0f);
        float p = t * t;
        float4 vv = *(const float4*)(vg + (size_t)sidx[wid][c] * D_);
        acc.x = fmaf(p, vv.x, acc.x); acc.y = fmaf(p, vv.y, acc.y);
        acc.z = fmaf(p, vv.z, acc.z); acc.w = fmaf(p, vv.w, acc.w);
    }
    *(float4*)(out + row * D_ + (lane << 2)) = acc;
}

// ---------------------------------------------------------------------------
extern "C" void kernel_launch(void* const* d_in, const int* in_sizes, int n_in,
                              void* d_out, int out_size) {
    (void)in_sizes; (void)n_in; (void)out_size;
    const float* q    = (const float*)d_in[0];
    const float* k    = (const float*)d_in[1];
    const float* v    = (const float*)d_in[2];
    const int*   mask = (const int*)d_in[3];
    float*       out  = (float*)d_out;

    constexpr int QK_SMEM = 30720;
    cudaFuncSetAttribute(qk_kernel, cudaFuncAttributeMaxDynamicSharedMemorySize, QK_SMEM);

    qk_kernel<<<dim3(16, 8, BH_), 256, QK_SMEM>>>(q, k, mask);
    select_refine_kernel<<<BH_ * S_ / 8, 256>>>(q, k, v, mask, out);
}